// round 2
// baseline (speedup 1.0000x reference)
#include <cuda_runtime.h>

typedef unsigned long long u64;

#define B_  128
#define T_  512
#define D_  300
#define DP  304   // D padded to multiple of 16
#define H_  128
#define V_  50000

// ---------------- static device scratch ----------------
__device__ float g_xemb[(size_t)B_ * T_ * DP];      // gathered embeddings, padded
__device__ float g_xg0 [(size_t)B_ * T_ * 1024];    // layer0 input preacts (fwd 0:512, rev 512:1024)
__device__ float g_h0  [(size_t)B_ * T_ * 256];     // layer0 output (fwd 0:128, rev 128:256)
__device__ float g_xg1 [(size_t)B_ * T_ * 512];     // layer1-fwd input preacts
__device__ float g_h1f [B_ * H_];                   // layer1-fwd final hidden
__device__ float g_Bt1 [DP * 1024];                 // packed W_ih layer0, [k][n]
__device__ float g_bias0[1024];
__device__ float g_Bt2 [256 * 512];                 // packed W_ih layer1-fwd, [k][n]
__device__ float g_bias1[512];

// ---------------- helpers ----------------
__device__ __forceinline__ u64 fma2(u64 a, u64 b, u64 c) {
    u64 d;
    asm("fma.rn.f32x2 %0, %1, %2, %3;" : "=l"(d) : "l"(a), "l"(b), "l"(c));
    return d;
}
union F2U { float2 f; u64 u; };
__device__ __forceinline__ u64 f2u(float x, float y) { F2U v; v.f = make_float2(x, y); return v.u; }
__device__ __forceinline__ float2 u2f(u64 u) { F2U v; v.u = u; return v.f; }

__device__ __forceinline__ float sigf_(float x) {
    return __fdividef(1.0f, 1.0f + __expf(-x));
}
__device__ __forceinline__ float tanhf_(float x) {
    // 1 - 2/(e^{2x}+1); saturates correctly at +-inf
    float e = __expf(2.0f * x);
    return 1.0f - __fdividef(2.0f, e + 1.0f);
}

// ---------------- weight packing ----------------
__global__ void prep_kernel(const float* __restrict__ wih0f, const float* __restrict__ wih0r,
                            const float* __restrict__ bih0f, const float* __restrict__ bhh0f,
                            const float* __restrict__ bih0r, const float* __restrict__ bhh0r,
                            const float* __restrict__ wih1f,
                            const float* __restrict__ bih1f, const float* __restrict__ bhh1f)
{
    int idx = blockIdx.x * blockDim.x + threadIdx.x;
    const int total1 = DP * 1024;
    if (idx < total1) {
        int k = idx >> 10, n = idx & 1023;
        float v = 0.0f;
        if (k < D_) v = (n < 512) ? wih0f[n * D_ + k] : wih0r[(n - 512) * D_ + k];
        g_Bt1[idx] = v;
    }
    if (idx < 256 * 512) {
        int k = idx >> 9, n = idx & 511;
        g_Bt2[idx] = wih1f[n * 256 + k];
    }
    if (idx < 1024)
        g_bias0[idx] = (idx < 512) ? (bih0f[idx] + bhh0f[idx])
                                   : (bih0r[idx - 512] + bhh0r[idx - 512]);
    if (idx < 512)
        g_bias1[idx] = bih1f[idx] + bhh1f[idx];
}

// ---------------- embedding gather (padded to DP) ----------------
__global__ void embed_kernel(const int* __restrict__ x, const float* __restrict__ emb)
{
    int bt = blockIdx.x;
    int d = threadIdx.x;
    if (d < DP) {
        int ix = x[bt];
        float v = 0.0f;
        if (d < D_) v = emb[(size_t)ix * D_ + d];
        g_xemb[(size_t)bt * DP + d] = v;
    }
}

// ---------------- SGEMM (fma2): C[65536][N] = A[65536][K] * B[K][N] + bias[N] ----------------
__global__ __launch_bounds__(256) void sgemm_bias(
    const float* __restrict__ A, const float* __restrict__ B,
    const float* __restrict__ bias, float* __restrict__ C,
    int N, int K)
{
    __shared__ float As[16][128];
    __shared__ float Bs[16][128];
    int tid = threadIdx.x;
    int m0 = blockIdx.x * 128, n0 = blockIdx.y * 128;
    int am = tid & 127, ak = (tid >> 7) * 8;
    int bn = (tid & 31) * 4, bk = tid >> 5;
    int tx8 = (tid & 15) * 8, ty8 = (tid >> 4) * 8;

    u64 acc[32];
#pragma unroll
    for (int i = 0; i < 32; i++) acc[i] = 0ull;

    const float* Aptr = A + (size_t)(m0 + am) * K + ak;
    const float* Bptr = B + (size_t)bk * N + n0 + bn;

    for (int kt = 0; kt < K; kt += 16) {
        float4 a0 = *(const float4*)(Aptr + kt);
        float4 a1 = *(const float4*)(Aptr + kt + 4);
        float4 bv0 = *(const float4*)(Bptr + (size_t)kt * N);
        float4 bv1 = *(const float4*)(Bptr + (size_t)(kt + 8) * N);
        __syncthreads();
        As[ak + 0][am] = a0.x; As[ak + 1][am] = a0.y;
        As[ak + 2][am] = a0.z; As[ak + 3][am] = a0.w;
        As[ak + 4][am] = a1.x; As[ak + 5][am] = a1.y;
        As[ak + 6][am] = a1.z; As[ak + 7][am] = a1.w;
        *(float4*)&Bs[bk][bn] = bv0;
        *(float4*)&Bs[bk + 8][bn] = bv1;
        __syncthreads();
#pragma unroll
        for (int kk = 0; kk < 16; kk++) {
            float4 A01 = *(const float4*)&As[kk][ty8];
            float4 A23 = *(const float4*)&As[kk][ty8 + 4];
            float4 B01 = *(const float4*)&Bs[kk][tx8];
            float4 B23 = *(const float4*)&Bs[kk][tx8 + 4];
            u64 bp0 = f2u(B01.x, B01.y), bp1 = f2u(B01.z, B01.w);
            u64 bp2 = f2u(B23.x, B23.y), bp3 = f2u(B23.z, B23.w);
            float av[8] = {A01.x, A01.y, A01.z, A01.w, A23.x, A23.y, A23.z, A23.w};
#pragma unroll
            for (int i = 0; i < 8; i++) {
                u64 ad = f2u(av[i], av[i]);
                acc[i * 4 + 0] = fma2(ad, bp0, acc[i * 4 + 0]);
                acc[i * 4 + 1] = fma2(ad, bp1, acc[i * 4 + 1]);
                acc[i * 4 + 2] = fma2(ad, bp2, acc[i * 4 + 2]);
                acc[i * 4 + 3] = fma2(ad, bp3, acc[i * 4 + 3]);
            }
        }
    }
    float bb[8];
#pragma unroll
    for (int j = 0; j < 8; j++) bb[j] = bias[n0 + tx8 + j];
#pragma unroll
    for (int i = 0; i < 8; i++) {
        float2 r0 = u2f(acc[i * 4 + 0]), r1 = u2f(acc[i * 4 + 1]);
        float2 r2 = u2f(acc[i * 4 + 2]), r3 = u2f(acc[i * 4 + 3]);
        float4 o0 = make_float4(r0.x + bb[0], r0.y + bb[1], r1.x + bb[2], r1.y + bb[3]);
        float4 o1 = make_float4(r2.x + bb[4], r2.y + bb[5], r3.x + bb[6], r3.y + bb[7]);
        size_t row = (size_t)(m0 + ty8 + i);
        *(float4*)(C + row * N + n0 + tx8) = o0;
        *(float4*)(C + row * N + n0 + tx8 + 4) = o1;
    }
}

// ---------------- LSTM recurrence ----------------
// One CTA handles NB batch elements of one direction. 512 threads, thread g owns gate row g.
// W_hh row split: cols 0..71 in registers (36 f32x2 pairs), cols 72..127 in smem
// (14 float4 columns, layout ws4[q][512] -> conflict-free LDS.128).
#define QREG 18   // float4 groups held in registers (18*4 = 72 cols)
#define QSM  14   // float4 groups held in smem     (14*4 = 56 cols)

template<bool STORE_ALL, int NB>
__global__ __launch_bounds__(512, 1) void lstm_rec(
    const float* __restrict__ xg, int xg_stride, int goff_per_dir,
    const float* __restrict__ whh_f, const float* __restrict__ whh_r,
    float* __restrict__ hout, int hout_stride, int hcol_per_dir)
{
    extern __shared__ float sm[];
    float4* ws4  = (float4*)sm;                      // [QSM][512]
    float*  h_sm = sm + QSM * 512 * 4;               // [NB][128]
    float*  gates = h_sm + NB * 128;                 // [NB][512]

    const int g = threadIdx.x;
    const int dir = blockIdx.y;
    const int b0 = blockIdx.x * NB;
    const int rev = dir;
    const float* whh = dir ? whh_r : whh_f;
    const int goff = dir * goff_per_dir;

    // load W_hh row g
    u64 wreg[2 * QREG];
    const float4* wrow = (const float4*)(whh + (size_t)g * 128);
#pragma unroll
    for (int q = 0; q < QREG; q++) {
        float4 v = wrow[q];
        wreg[2 * q]     = f2u(v.x, v.y);
        wreg[2 * q + 1] = f2u(v.z, v.w);
    }
#pragma unroll
    for (int q = 0; q < QSM; q++)
        ws4[q * 512 + g] = wrow[QREG + q];

    if (g < NB * 128) h_sm[g] = 0.0f;
    float creg = 0.0f;
    __syncthreads();

    for (int s = 0; s < T_; s++) {
        int t = rev ? (T_ - 1 - s) : s;
        float xv[NB];
#pragma unroll
        for (int u = 0; u < NB; u++)
            xv[u] = xg[(size_t)((b0 + u) * T_ + t) * xg_stride + goff + g];

        u64 acc[NB];
#pragma unroll
        for (int u = 0; u < NB; u++) acc[u] = 0ull;

#pragma unroll
        for (int q = 0; q < QREG; q++) {
#pragma unroll
            for (int u = 0; u < NB; u++) {
                float4 h = *(const float4*)(h_sm + u * 128 + q * 4);
                acc[u] = fma2(wreg[2 * q],     f2u(h.x, h.y), acc[u]);
                acc[u] = fma2(wreg[2 * q + 1], f2u(h.z, h.w), acc[u]);
            }
        }
#pragma unroll
        for (int q = 0; q < QSM; q++) {
            float4 w = ws4[q * 512 + g];
            u64 w01 = f2u(w.x, w.y), w23 = f2u(w.z, w.w);
#pragma unroll
            for (int u = 0; u < NB; u++) {
                float4 h = *(const float4*)(h_sm + u * 128 + (QREG + q) * 4);
                acc[u] = fma2(w01, f2u(h.x, h.y), acc[u]);
                acc[u] = fma2(w23, f2u(h.z, h.w), acc[u]);
            }
        }
#pragma unroll
        for (int u = 0; u < NB; u++) {
            float2 a = u2f(acc[u]);
            gates[u * 512 + g] = a.x + a.y + xv[u];
        }
        __syncthreads();

        if (g < NB * 128) {
            int bb = g >> 7, n = g & 127;
            const float* gs = gates + bb * 512;
            float iv = sigf_(gs[n]);
            float fv = sigf_(gs[n + 128]);
            float gv = tanhf_(gs[n + 256]);
            float ov = sigf_(gs[n + 384]);
            creg = fv * creg + iv * gv;
            float hv = ov * tanhf_(creg);
            h_sm[bb * 128 + n] = hv;
            int b = b0 + bb;
            if (STORE_ALL) {
                hout[(size_t)(b * T_ + t) * hout_stride + dir * hcol_per_dir + n] = hv;
            } else if (s == T_ - 1) {
                hout[b * H_ + n] = hv;
            }
        }
        __syncthreads();
    }
}

// ---------------- layer1 reverse (first step only) + FC head ----------------
__global__ __launch_bounds__(256) void tail_kernel(
    const float* __restrict__ h0, const float* __restrict__ h1f,
    const float* __restrict__ wih_r, const float* __restrict__ bih_r,
    const float* __restrict__ bhh_r,
    const float* __restrict__ fc_w, const float* __restrict__ fc_b,
    float* __restrict__ out)
{
    __shared__ float hl[256];
    __shared__ float hcat[256];
    __shared__ float gsm[512];
    int b = blockIdx.x, tid = threadIdx.x;
    hl[tid] = h0[(size_t)(b * T_ + (T_ - 1)) * 256 + tid];
    __syncthreads();

#pragma unroll
    for (int r = 0; r < 2; r++) {
        int g = tid + r * 256;
        u64 acc = 0ull;
        const float4* wr = (const float4*)(wih_r + (size_t)g * 256);
        const float4* hp = (const float4*)hl;
#pragma unroll 8
        for (int q = 0; q < 64; q++) {
            float4 w = wr[q];
            float4 h = hp[q];
            acc = fma2(f2u(w.x, w.y), f2u(h.x, h.y), acc);
            acc = fma2(f2u(w.z, w.w), f2u(h.z, h.w), acc);
        }
        float2 a = u2f(acc);
        gsm[g] = a.x + a.y + bih_r[g] + bhh_r[g];
    }
    __syncthreads();

    if (tid < 128) {
        float iv = sigf_(gsm[tid]);
        float gv = tanhf_(gsm[tid + 256]);
        float ov = sigf_(gsm[tid + 384]);
        float c = iv * gv;                 // f*c_prev = 0 on first reverse step
        hcat[128 + tid] = ov * tanhf_(c);
        hcat[tid] = h1f[b * 128 + tid];
    }
    __syncthreads();

    if (tid < 10) {
        float acc = fc_b[tid];
        const float* w = fc_w + tid * 256;
#pragma unroll 8
        for (int j = 0; j < 256; j++) acc += w[j] * hcat[j];
        out[b * 10 + tid] = acc;
    }
}

// ---------------- launch ----------------
extern "C" void kernel_launch(void* const* d_in, const int* in_sizes, int n_in,
                              void* d_out, int out_size)
{
    const int*   x     = (const int*)d_in[0];
    const float* emb   = (const float*)d_in[1];
    const float* wih0f = (const float*)d_in[2];
    const float* whh0f = (const float*)d_in[3];
    const float* bih0f = (const float*)d_in[4];
    const float* bhh0f = (const float*)d_in[5];
    const float* wih0r = (const float*)d_in[6];
    const float* whh0r = (const float*)d_in[7];
    const float* bih0r = (const float*)d_in[8];
    const float* bhh0r = (const float*)d_in[9];
    const float* wih1f = (const float*)d_in[10];
    const float* whh1f = (const float*)d_in[11];
    const float* bih1f = (const float*)d_in[12];
    const float* bhh1f = (const float*)d_in[13];
    const float* wih1r = (const float*)d_in[14];
    const float* bih1r = (const float*)d_in[16];
    const float* bhh1r = (const float*)d_in[17];
    const float* fc_w  = (const float*)d_in[18];
    const float* fc_b  = (const float*)d_in[19];
    float* out = (float*)d_out;

    float *xemb_p, *xg0_p, *h0_p, *xg1_p, *h1f_p, *Bt1_p, *bias0_p, *Bt2_p, *bias1_p;
    cudaGetSymbolAddress((void**)&xemb_p,  g_xemb);
    cudaGetSymbolAddress((void**)&xg0_p,   g_xg0);
    cudaGetSymbolAddress((void**)&h0_p,    g_h0);
    cudaGetSymbolAddress((void**)&xg1_p,   g_xg1);
    cudaGetSymbolAddress((void**)&h1f_p,   g_h1f);
    cudaGetSymbolAddress((void**)&Bt1_p,   g_Bt1);
    cudaGetSymbolAddress((void**)&bias0_p, g_bias0);
    cudaGetSymbolAddress((void**)&Bt2_p,   g_Bt2);
    cudaGetSymbolAddress((void**)&bias1_p, g_bias1);

    const int rec_smem = QSM * 512 * 16 + 2 * 128 * 4 + 2 * 512 * 4;  // 119,808 B
    cudaFuncSetAttribute(lstm_rec<true, 2>,  cudaFuncAttributeMaxDynamicSharedMemorySize, rec_smem);
    cudaFuncSetAttribute(lstm_rec<false, 1>, cudaFuncAttributeMaxDynamicSharedMemorySize, rec_smem);

    // 1. pack weights
    prep_kernel<<<(DP * 1024 + 255) / 256, 256>>>(wih0f, wih0r, bih0f, bhh0f,
                                                  bih0r, bhh0r, wih1f, bih1f, bhh1f);
    // 2. embedding gather
    embed_kernel<<<B_ * T_, 320>>>(x, emb);
    // 3. layer0 input GEMM: [65536,304] x [304,1024]
    sgemm_bias<<<dim3(512, 8), 256>>>(xemb_p, Bt1_p, bias0_p, xg0_p, 1024, DP);
    // 4. layer0 recurrence (both dirs, 2 batch/CTA -> 128 CTAs)
    lstm_rec<true, 2><<<dim3(64, 2), 512, rec_smem>>>(
        xg0_p, 1024, 512, whh0f, whh0r, h0_p, 256, 128);
    // 5. layer1-fwd input GEMM: [65536,256] x [256,512]
    sgemm_bias<<<dim3(512, 4), 256>>>(h0_p, Bt2_p, bias1_p, xg1_p, 512, 256);
    // 6. layer1-fwd recurrence (1 batch/CTA -> 128 CTAs), keep only final h
    lstm_rec<false, 1><<<dim3(128, 1), 512, rec_smem>>>(
        xg1_p, 512, 0, whh1f, whh1f, h1f_p, 0, 0);
    // 7. layer1-rev first step + FC head
    tail_kernel<<<B_, 256>>>(h0_p, h1f_p, wih1r, bih1r, bhh1r, fc_w, fc_b, out);
}

// round 4
// speedup vs baseline: 1.2798x; 1.2798x over previous
#include <cuda_runtime.h>
#include <cuda_bf16.h>

typedef unsigned long long u64;
typedef unsigned int u32;

#define B_  128
#define T_  512
#define D_  300
#define H_  128
#define KP1 320   // layer0 K padded (300 -> 320, 10 chunks of 32)
#define KP2 256   // layer1 K (8 chunks of 32)

// ---------------- static device scratch ----------------
__device__ __nv_bfloat16 g_Ah [(size_t)B_ * T_ * KP1];   // embeddings bf16 hi
__device__ __nv_bfloat16 g_Al [(size_t)B_ * T_ * KP1];   // embeddings bf16 lo
__device__ float g_xg0 [(size_t)B_ * T_ * 1024];         // layer0 preacts (fwd 0:512, rev 512:1024)
__device__ float g_h0  [(size_t)B_ * T_ * 256];          // layer0 output fp32
__device__ __nv_bfloat16 g_h0h[(size_t)B_ * T_ * 256];   // layer0 output bf16 hi
__device__ __nv_bfloat16 g_h0l[(size_t)B_ * T_ * 256];   // layer0 output bf16 lo
__device__ float g_xg1 [(size_t)B_ * T_ * 512];          // layer1-fwd preacts
__device__ float g_h1f [B_ * H_];
__device__ __nv_bfloat16 g_B1h[1024 * KP1];              // W_ih layer0 (f||r), [n][k]
__device__ __nv_bfloat16 g_B1l[1024 * KP1];
__device__ __nv_bfloat16 g_B2h[512 * KP2];               // W_ih layer1-fwd, [n][k]
__device__ __nv_bfloat16 g_B2l[512 * KP2];
__device__ float g_bias0[1024];
__device__ float g_bias1[512];

// ---------------- scalar helpers ----------------
__device__ __forceinline__ u64 fma2(u64 a, u64 b, u64 c) {
    u64 d;
    asm("fma.rn.f32x2 %0, %1, %2, %3;" : "=l"(d) : "l"(a), "l"(b), "l"(c));
    return d;
}
union F2U { float2 f; u64 u; };
__device__ __forceinline__ u64 f2u(float x, float y) { F2U v; v.f = make_float2(x, y); return v.u; }
__device__ __forceinline__ float2 u2f(u64 u) { F2U v; v.u = u; return v.f; }

__device__ __forceinline__ float sigf_(float x) {
    return __fdividef(1.0f, 1.0f + __expf(-x));
}
__device__ __forceinline__ float tanhf_(float x) {
    float e = __expf(2.0f * x);
    return 1.0f - __fdividef(2.0f, e + 1.0f);
}
__device__ __forceinline__ void bsplit(float v, __nv_bfloat16& hi, __nv_bfloat16& lo) {
    hi = __float2bfloat16(v);
    lo = __float2bfloat16(v - __bfloat162float(hi));
}

__device__ __forceinline__ u32 smem_u32(const void* p) {
    u32 a;
    asm("{ .reg .u64 t; cvta.to.shared.u64 t, %1; cvt.u32.u64 %0, t; }" : "=r"(a) : "l"(p));
    return a;
}

// ---------------- warp-MMA primitives (baseline PTX, no sm_103a features) ----------------
#define LDSM4(r0, r1, r2, r3, addr)                                         \
    asm volatile("ldmatrix.sync.aligned.m8n8.x4.shared.b16 {%0,%1,%2,%3}, [%4];" \
        : "=r"(r0), "=r"(r1), "=r"(r2), "=r"(r3) : "r"(addr))

#define MMA16816(d, a, b)                                                   \
    asm volatile("mma.sync.aligned.m16n8k16.row.col.f32.bf16.bf16.f32 "     \
        "{%0,%1,%2,%3}, {%4,%5,%6,%7}, {%8,%9}, {%0,%1,%2,%3};"             \
        : "+f"((d)[0]), "+f"((d)[1]), "+f"((d)[2]), "+f"((d)[3])            \
        : "r"((a)[0]), "r"((a)[1]), "r"((a)[2]), "r"((a)[3]),               \
          "r"((b)[0]), "r"((b)[1]))

// ---------------- weight prep ----------------
__global__ void prep_kernel(const float* __restrict__ wih0f, const float* __restrict__ wih0r,
                            const float* __restrict__ wih1f,
                            const float* __restrict__ bih0f, const float* __restrict__ bhh0f,
                            const float* __restrict__ bih0r, const float* __restrict__ bhh0r,
                            const float* __restrict__ bih1f, const float* __restrict__ bhh1f)
{
    int idx = blockIdx.x * 256 + threadIdx.x;
    if (idx < 1024 * KP1) {
        int n = idx / KP1, k = idx - n * KP1;
        float v = 0.0f;
        if (k < D_) v = (n < 512) ? wih0f[n * D_ + k] : wih0r[(n - 512) * D_ + k];
        __nv_bfloat16 hi, lo; bsplit(v, hi, lo);
        g_B1h[idx] = hi; g_B1l[idx] = lo;
    }
    if (idx < 512 * KP2) {
        __nv_bfloat16 hi, lo; bsplit(wih1f[idx], hi, lo);
        g_B2h[idx] = hi; g_B2l[idx] = lo;
    }
    if (idx < 1024)
        g_bias0[idx] = (idx < 512) ? (bih0f[idx] + bhh0f[idx])
                                   : (bih0r[idx - 512] + bhh0r[idx - 512]);
    if (idx < 512)
        g_bias1[idx] = bih1f[idx] + bhh1f[idx];
}

// ---------------- embedding gather -> bf16 hi/lo ----------------
__global__ void embed_kernel(const int* __restrict__ x, const float* __restrict__ emb)
{
    int bt = blockIdx.x;
    int d = threadIdx.x;   // 320 threads
    int ix = x[bt];
    float v = (d < D_) ? emb[(size_t)ix * D_ + d] : 0.0f;
    __nv_bfloat16 hi, lo; bsplit(v, hi, lo);
    g_Ah[(size_t)bt * KP1 + d] = hi;
    g_Al[(size_t)bt * KP1 + d] = lo;
}

// ---------------- HMMA GEMM: C[M][N] = A*B^T + bias, bf16 2-term split ----------------
// CTA 128x128, 8 warps (4 M x 2 N), warp tile 32x64, K-chunk 32.
// smem rows padded to 40 bf16 (80 B) -> conflict-free ldmatrix.
#define PADK 40

__global__ __launch_bounds__(256, 1) void gemm_mma(
    const __nv_bfloat16* __restrict__ Ah, const __nv_bfloat16* __restrict__ Al,
    const __nv_bfloat16* __restrict__ Bh, const __nv_bfloat16* __restrict__ Bl,
    const float* __restrict__ bias, float* __restrict__ C,
    int Kpad, int NC, int N)
{
    __shared__ __nv_bfloat16 sAh[128 * PADK], sAl[128 * PADK];
    __shared__ __nv_bfloat16 sBh[128 * PADK], sBl[128 * PADK];

    const int tid = threadIdx.x;
    const int lid = tid & 31, wid = tid >> 5;
    const int wm = wid & 3, wn = wid >> 2;
    const int m0 = blockIdx.y * 128, n0 = blockIdx.x * 128;

    // global-load mapping: thread loads rows (t>>2, t>>2 + 64), cols (t&3)*8
    const int gr = tid >> 2, gc = (tid & 3) * 8;
    const __nv_bfloat16* pAh0 = Ah + (size_t)(m0 + gr) * Kpad + gc;
    const __nv_bfloat16* pAl0 = Al + (size_t)(m0 + gr) * Kpad + gc;
    const __nv_bfloat16* pBh0 = Bh + (size_t)(n0 + gr) * Kpad + gc;
    const __nv_bfloat16* pBl0 = Bl + (size_t)(n0 + gr) * Kpad + gc;
    const size_t rstep = (size_t)64 * Kpad;

    // ldmatrix per-thread source offsets (bytes), within a [128][PADK] bf16 tile
    const int aRow = wm * 32 + (lid & 7) + ((lid >> 3) & 1) * 8;
    const int aK   = (lid >> 4) * 8;
    const int bRow = wn * 64 + (lid & 7) + ((lid >> 4) & 1) * 8;
    const int bK   = ((lid >> 3) & 1) * 8;
    const u32 sAh_b = smem_u32(sAh), sAl_b = smem_u32(sAl);
    const u32 sBh_b = smem_u32(sBh), sBl_b = smem_u32(sBl);
    const u32 aOff = (u32)(aRow * (PADK * 2) + aK * 2);
    const u32 bOff = (u32)(bRow * (PADK * 2) + bK * 2);

    float acc[2][8][4];
#pragma unroll
    for (int mt = 0; mt < 2; mt++)
#pragma unroll
        for (int nt = 0; nt < 8; nt++)
#pragma unroll
            for (int j = 0; j < 4; j++) acc[mt][nt][j] = 0.0f;

    uint4 ra[2], rl[2], rb[2], rbl[2];
#pragma unroll
    for (int i = 0; i < 2; i++) {
        ra[i]  = *(const uint4*)(pAh0 + i * rstep);
        rl[i]  = *(const uint4*)(pAl0 + i * rstep);
        rb[i]  = *(const uint4*)(pBh0 + i * rstep);
        rbl[i] = *(const uint4*)(pBl0 + i * rstep);
    }

    for (int c = 0; c < NC; c++) {
        __syncthreads();
#pragma unroll
        for (int i = 0; i < 2; i++) {
            int so = (gr + i * 64) * PADK + gc;
            *(uint4*)(sAh + so) = ra[i];
            *(uint4*)(sAl + so) = rl[i];
            *(uint4*)(sBh + so) = rb[i];
            *(uint4*)(sBl + so) = rbl[i];
        }
        __syncthreads();
        if (c + 1 < NC) {
            int k0 = (c + 1) * 32;
#pragma unroll
            for (int i = 0; i < 2; i++) {
                ra[i]  = *(const uint4*)(pAh0 + i * rstep + k0);
                rl[i]  = *(const uint4*)(pAl0 + i * rstep + k0);
                rb[i]  = *(const uint4*)(pBh0 + i * rstep + k0);
                rbl[i] = *(const uint4*)(pBl0 + i * rstep + k0);
            }
        }
#pragma unroll
        for (int ks = 0; ks < 2; ks++) {
            const u32 kso = ks * 32;   // 16 elems * 2 bytes
            u32 afh[2][4], afl[2][4];
#pragma unroll
            for (int mt = 0; mt < 2; mt++) {
                u32 off = aOff + mt * 16 * (PADK * 2) + kso;
                LDSM4(afh[mt][0], afh[mt][1], afh[mt][2], afh[mt][3], sAh_b + off);
                LDSM4(afl[mt][0], afl[mt][1], afl[mt][2], afl[mt][3], sAl_b + off);
            }
            u32 bfh[4][4], bfl[4][4];
#pragma unroll
            for (int np = 0; np < 4; np++) {
                u32 off = bOff + np * 16 * (PADK * 2) + kso;
                LDSM4(bfh[np][0], bfh[np][1], bfh[np][2], bfh[np][3], sBh_b + off);
                LDSM4(bfl[np][0], bfl[np][1], bfl[np][2], bfl[np][3], sBl_b + off);
            }
#pragma unroll
            for (int mt = 0; mt < 2; mt++) {
#pragma unroll
                for (int np = 0; np < 4; np++) {
#pragma unroll
                    for (int hf = 0; hf < 2; hf++) {
                        int nt = np * 2 + hf;
                        u32 bh[2] = { bfh[np][hf * 2], bfh[np][hf * 2 + 1] };
                        u32 bl[2] = { bfl[np][hf * 2], bfl[np][hf * 2 + 1] };
                        MMA16816(acc[mt][nt], afh[mt], bh);
                        MMA16816(acc[mt][nt], afh[mt], bl);
                        MMA16816(acc[mt][nt], afl[mt], bh);
                    }
                }
            }
        }
    }

    // epilogue
    const int qr = lid >> 2, qc = (lid & 3) * 2;
#pragma unroll
    for (int mt = 0; mt < 2; mt++) {
#pragma unroll
        for (int nt = 0; nt < 8; nt++) {
            int row = m0 + wm * 32 + mt * 16 + qr;
            int col = n0 + wn * 64 + nt * 8 + qc;
            float b0 = bias[col], b1 = bias[col + 1];
            float2 o0 = make_float2(acc[mt][nt][0] + b0, acc[mt][nt][1] + b1);
            float2 o1 = make_float2(acc[mt][nt][2] + b0, acc[mt][nt][3] + b1);
            *(float2*)(C + (size_t)row * N + col) = o0;
            *(float2*)(C + (size_t)(row + 8) * N + col) = o1;
        }
    }
}

// ---------------- LSTM recurrence ----------------
#define QREG 18
#define QSM  14

template<bool STORE_ALL, int NB>
__global__ __launch_bounds__(512, 1) void lstm_rec(
    const float* __restrict__ xg, int xg_stride, int goff_per_dir,
    const float* __restrict__ whh_f, const float* __restrict__ whh_r,
    float* __restrict__ hout, int hout_stride, int hcol_per_dir)
{
    extern __shared__ float sm[];
    float4* ws4  = (float4*)sm;
    float*  h_sm = sm + QSM * 512 * 4;
    float*  gates = h_sm + NB * 128;

    const int g = threadIdx.x;
    const int dir = blockIdx.y;
    const int b0 = blockIdx.x * NB;
    const int rev = dir;
    const float* whh = dir ? whh_r : whh_f;
    const int goff = dir * goff_per_dir;

    u64 wreg[2 * QREG];
    const float4* wrow = (const float4*)(whh + (size_t)g * 128);
#pragma unroll
    for (int q = 0; q < QREG; q++) {
        float4 v = wrow[q];
        wreg[2 * q]     = f2u(v.x, v.y);
        wreg[2 * q + 1] = f2u(v.z, v.w);
    }
#pragma unroll
    for (int q = 0; q < QSM; q++)
        ws4[q * 512 + g] = wrow[QREG + q];

    if (g < NB * 128) h_sm[g] = 0.0f;
    float creg = 0.0f;
    __syncthreads();

    for (int s = 0; s < T_; s++) {
        int t = rev ? (T_ - 1 - s) : s;
        float xv[NB];
#pragma unroll
        for (int u = 0; u < NB; u++)
            xv[u] = xg[(size_t)((b0 + u) * T_ + t) * xg_stride + goff + g];

        u64 acc[NB];
#pragma unroll
        for (int u = 0; u < NB; u++) acc[u] = 0ull;

#pragma unroll
        for (int q = 0; q < QREG; q++) {
#pragma unroll
            for (int u = 0; u < NB; u++) {
                float4 h = *(const float4*)(h_sm + u * 128 + q * 4);
                acc[u] = fma2(wreg[2 * q],     f2u(h.x, h.y), acc[u]);
                acc[u] = fma2(wreg[2 * q + 1], f2u(h.z, h.w), acc[u]);
            }
        }
#pragma unroll
        for (int q = 0; q < QSM; q++) {
            float4 w = ws4[q * 512 + g];
            u64 w01 = f2u(w.x, w.y), w23 = f2u(w.z, w.w);
#pragma unroll
            for (int u = 0; u < NB; u++) {
                float4 h = *(const float4*)(h_sm + u * 128 + (QREG + q) * 4);
                acc[u] = fma2(w01, f2u(h.x, h.y), acc[u]);
                acc[u] = fma2(w23, f2u(h.z, h.w), acc[u]);
            }
        }
#pragma unroll
        for (int u = 0; u < NB; u++) {
            float2 a = u2f(acc[u]);
            gates[u * 512 + g] = a.x + a.y + xv[u];
        }
        __syncthreads();

        if (g < NB * 128) {
            int bb = g >> 7, n = g & 127;
            const float* gs = gates + bb * 512;
            float iv = sigf_(gs[n]);
            float fv = sigf_(gs[n + 128]);
            float gv = tanhf_(gs[n + 256]);
            float ov = sigf_(gs[n + 384]);
            creg = fv * creg + iv * gv;
            float hv = ov * tanhf_(creg);
            h_sm[bb * 128 + n] = hv;
            int b = b0 + bb;
            if (STORE_ALL) {
                size_t o = (size_t)(b * T_ + t) * hout_stride + dir * hcol_per_dir + n;
                hout[o] = hv;
                __nv_bfloat16 hi, lo; bsplit(hv, hi, lo);
                g_h0h[o] = hi;
                g_h0l[o] = lo;
            } else if (s == T_ - 1) {
                hout[b * H_ + n] = hv;
            }
        }
        __syncthreads();
    }
}

// ---------------- layer1 reverse (first step only) + FC head ----------------
__global__ __launch_bounds__(256) void tail_kernel(
    const float* __restrict__ h0, const float* __restrict__ h1f,
    const float* __restrict__ wih_r, const float* __restrict__ bih_r,
    const float* __restrict__ bhh_r,
    const float* __restrict__ fc_w, const float* __restrict__ fc_b,
    float* __restrict__ out)
{
    __shared__ float hl[256];
    __shared__ float hcat[256];
    __shared__ float gsm[512];
    int b = blockIdx.x, tid = threadIdx.x;
    hl[tid] = h0[(size_t)(b * T_ + (T_ - 1)) * 256 + tid];
    __syncthreads();

#pragma unroll
    for (int r = 0; r < 2; r++) {
        int g = tid + r * 256;
        u64 acc = 0ull;
        const float4* wr = (const float4*)(wih_r + (size_t)g * 256);
        const float4* hp = (const float4*)hl;
#pragma unroll 8
        for (int q = 0; q < 64; q++) {
            float4 w = wr[q];
            float4 h = hp[q];
            acc = fma2(f2u(w.x, w.y), f2u(h.x, h.y), acc);
            acc = fma2(f2u(w.z, w.w), f2u(h.z, h.w), acc);
        }
        float2 a = u2f(acc);
        gsm[g] = a.x + a.y + bih_r[g] + bhh_r[g];
    }
    __syncthreads();

    if (tid < 128) {
        float iv = sigf_(gsm[tid]);
        float gv = tanhf_(gsm[tid + 256]);
        float ov = sigf_(gsm[tid + 384]);
        float c = iv * gv;
        hcat[128 + tid] = ov * tanhf_(c);
        hcat[tid] = h1f[b * 128 + tid];
    }
    __syncthreads();

    if (tid < 10) {
        float acc = fc_b[tid];
        const float* w = fc_w + tid * 256;
#pragma unroll 8
        for (int j = 0; j < 256; j++) acc += w[j] * hcat[j];
        out[b * 10 + tid] = acc;
    }
}

// ---------------- launch ----------------
extern "C" void kernel_launch(void* const* d_in, const int* in_sizes, int n_in,
                              void* d_out, int out_size)
{
    const int*   x     = (const int*)d_in[0];
    const float* emb   = (const float*)d_in[1];
    const float* wih0f = (const float*)d_in[2];
    const float* whh0f = (const float*)d_in[3];
    const float* bih0f = (const float*)d_in[4];
    const float* bhh0f = (const float*)d_in[5];
    const float* wih0r = (const float*)d_in[6];
    const float* whh0r = (const float*)d_in[7];
    const float* bih0r = (const float*)d_in[8];
    const float* bhh0r = (const float*)d_in[9];
    const float* wih1f = (const float*)d_in[10];
    const float* whh1f = (const float*)d_in[11];
    const float* bih1f = (const float*)d_in[12];
    const float* bhh1f = (const float*)d_in[13];
    const float* wih1r = (const float*)d_in[14];
    const float* bih1r = (const float*)d_in[16];
    const float* bhh1r = (const float*)d_in[17];
    const float* fc_w  = (const float*)d_in[18];
    const float* fc_b  = (const float*)d_in[19];
    float* out = (float*)d_out;

    void *Ah_p, *Al_p, *xg0_p, *h0_p, *h0h_p, *h0l_p, *xg1_p, *h1f_p;
    void *B1h_p, *B1l_p, *B2h_p, *B2l_p, *bias0_p, *bias1_p;
    cudaGetSymbolAddress(&Ah_p,   g_Ah);
    cudaGetSymbolAddress(&Al_p,   g_Al);
    cudaGetSymbolAddress(&xg0_p,  g_xg0);
    cudaGetSymbolAddress(&h0_p,   g_h0);
    cudaGetSymbolAddress(&h0h_p,  g_h0h);
    cudaGetSymbolAddress(&h0l_p,  g_h0l);
    cudaGetSymbolAddress(&xg1_p,  g_xg1);
    cudaGetSymbolAddress(&h1f_p,  g_h1f);
    cudaGetSymbolAddress(&B1h_p,  g_B1h);
    cudaGetSymbolAddress(&B1l_p,  g_B1l);
    cudaGetSymbolAddress(&B2h_p,  g_B2h);
    cudaGetSymbolAddress(&B2l_p,  g_B2l);
    cudaGetSymbolAddress(&bias0_p, g_bias0);
    cudaGetSymbolAddress(&bias1_p, g_bias1);

    const int rec_smem = QSM * 512 * 16 + 2 * 128 * 4 + 2 * 512 * 4;
    cudaFuncSetAttribute(lstm_rec<true, 2>,  cudaFuncAttributeMaxDynamicSharedMemorySize, rec_smem);
    cudaFuncSetAttribute(lstm_rec<false, 1>, cudaFuncAttributeMaxDynamicSharedMemorySize, rec_smem);

    // 1. weight prep (bf16 split + bias fold)
    prep_kernel<<<(1024 * KP1 + 255) / 256, 256>>>(wih0f, wih0r, wih1f,
                                                   bih0f, bhh0f, bih0r, bhh0r, bih1f, bhh1f);
    // 2. embedding gather -> bf16 hi/lo
    embed_kernel<<<B_ * T_, KP1>>>(x, emb);
    // 3. layer0 input GEMM (HMMA): [65536,320] x [320,1024]
    gemm_mma<<<dim3(8, 512), 256>>>(
        (const __nv_bfloat16*)Ah_p, (const __nv_bfloat16*)Al_p,
        (const __nv_bfloat16*)B1h_p, (const __nv_bfloat16*)B1l_p,
        (const float*)bias0_p, (float*)xg0_p, KP1, 10, 1024);
    // 4. layer0 recurrence
    lstm_rec<true, 2><<<dim3(64, 2), 512, rec_smem>>>(
        (const float*)xg0_p, 1024, 512, whh0f, whh0r, (float*)h0_p, 256, 128);
    // 5. layer1-fwd input GEMM (HMMA): [65536,256] x [256,512]
    gemm_mma<<<dim3(4, 512), 256>>>(
        (const __nv_bfloat16*)h0h_p, (const __nv_bfloat16*)h0l_p,
        (const __nv_bfloat16*)B2h_p, (const __nv_bfloat16*)B2l_p,
        (const float*)bias1_p, (float*)xg1_p, KP2, 8, 512);
    // 6. layer1-fwd recurrence
    lstm_rec<false, 1><<<dim3(128, 1), 512, rec_smem>>>(
        (const float*)xg1_p, 512, 0, whh1f, whh1f, (float*)h1f_p, 0, 0);
    // 7. layer1-rev first step + FC head
    tail_kernel<<<B_, 256>>>((const float*)h0_p, (const float*)h1f_p,
                             wih1r, bih1r, bhh1r, fc_w, fc_b, out);
}

// round 5
// speedup vs baseline: 1.4384x; 1.1239x over previous
#include <cuda_runtime.h>
#include <cuda_bf16.h>

typedef unsigned long long u64;
typedef unsigned int u32;

#define B_  128
#define T_  512
#define D_  300
#define H_  128
#define KP1 320   // layer0 K padded (300 -> 320, 10 chunks of 32)
#define KP2 256   // layer1 K (8 chunks of 32)

// ---------------- static device scratch ----------------
__device__ __nv_bfloat16 g_Ah [(size_t)B_ * T_ * KP1];   // embeddings bf16 hi
__device__ __nv_bfloat16 g_Al [(size_t)B_ * T_ * KP1];   // embeddings bf16 lo
__device__ float g_xg0 [(size_t)B_ * T_ * 1024];         // layer0 preacts (fwd 0:512, rev 512:1024)
__device__ float g_h0  [(size_t)B_ * T_ * 256];          // layer0 output fp32
__device__ __nv_bfloat16 g_h0h[(size_t)B_ * T_ * 256];   // layer0 output bf16 hi
__device__ __nv_bfloat16 g_h0l[(size_t)B_ * T_ * 256];   // layer0 output bf16 lo
__device__ float g_xg1 [(size_t)B_ * T_ * 512];          // layer1-fwd preacts
__device__ float g_h1f [B_ * H_];
__device__ __nv_bfloat16 g_B1h[1024 * KP1];              // W_ih layer0 (f||r), [n][k]
__device__ __nv_bfloat16 g_B1l[1024 * KP1];
__device__ __nv_bfloat16 g_B2h[512 * KP2];               // W_ih layer1-fwd, [n][k]
__device__ __nv_bfloat16 g_B2l[512 * KP2];
__device__ float g_bias0[1024];
__device__ float g_bias1[512];

// ---------------- scalar helpers ----------------
__device__ __forceinline__ u64 fma2(u64 a, u64 b, u64 c) {
    u64 d;
    asm("fma.rn.f32x2 %0, %1, %2, %3;" : "=l"(d) : "l"(a), "l"(b), "l"(c));
    return d;
}
union F2U { float2 f; u64 u; };
__device__ __forceinline__ u64 f2u(float x, float y) { F2U v; v.f = make_float2(x, y); return v.u; }
__device__ __forceinline__ float2 u2f(u64 u) { F2U v; v.u = u; return v.f; }

__device__ __forceinline__ float sigf_(float x) {
    return __fdividef(1.0f, 1.0f + __expf(-x));
}
__device__ __forceinline__ float tanhf_(float x) {
    float e = __expf(2.0f * x);
    return 1.0f - __fdividef(2.0f, e + 1.0f);
}
__device__ __forceinline__ void bsplit(float v, __nv_bfloat16& hi, __nv_bfloat16& lo) {
    hi = __float2bfloat16(v);
    lo = __float2bfloat16(v - __bfloat162float(hi));
}

__device__ __forceinline__ u32 smem_u32(const void* p) {
    u32 a;
    asm("{ .reg .u64 t; cvta.to.shared.u64 t, %1; cvt.u32.u64 %0, t; }" : "=r"(a) : "l"(p));
    return a;
}

// ---------------- warp-MMA primitives (baseline PTX, no sm_103a features) ----------------
#define LDSM4(r0, r1, r2, r3, addr)                                         \
    asm volatile("ldmatrix.sync.aligned.m8n8.x4.shared.b16 {%0,%1,%2,%3}, [%4];" \
        : "=r"(r0), "=r"(r1), "=r"(r2), "=r"(r3) : "r"(addr))

#define MMA16816(d, a, b)                                                   \
    asm volatile("mma.sync.aligned.m16n8k16.row.col.f32.bf16.bf16.f32 "     \
        "{%0,%1,%2,%3}, {%4,%5,%6,%7}, {%8,%9}, {%0,%1,%2,%3};"             \
        : "+f"((d)[0]), "+f"((d)[1]), "+f"((d)[2]), "+f"((d)[3])            \
        : "r"((a)[0]), "r"((a)[1]), "r"((a)[2]), "r"((a)[3]),               \
          "r"((b)[0]), "r"((b)[1]))

// ---------------- weight prep ----------------
__global__ void prep_kernel(const float* __restrict__ wih0f, const float* __restrict__ wih0r,
                            const float* __restrict__ wih1f,
                            const float* __restrict__ bih0f, const float* __restrict__ bhh0f,
                            const float* __restrict__ bih0r, const float* __restrict__ bhh0r,
                            const float* __restrict__ bih1f, const float* __restrict__ bhh1f)
{
    int idx = blockIdx.x * 256 + threadIdx.x;
    if (idx < 1024 * KP1) {
        int n = idx / KP1, k = idx - n * KP1;
        float v = 0.0f;
        if (k < D_) v = (n < 512) ? wih0f[n * D_ + k] : wih0r[(n - 512) * D_ + k];
        __nv_bfloat16 hi, lo; bsplit(v, hi, lo);
        g_B1h[idx] = hi; g_B1l[idx] = lo;
    }
    if (idx < 512 * KP2) {
        __nv_bfloat16 hi, lo; bsplit(wih1f[idx], hi, lo);
        g_B2h[idx] = hi; g_B2l[idx] = lo;
    }
    if (idx < 1024)
        g_bias0[idx] = (idx < 512) ? (bih0f[idx] + bhh0f[idx])
                                   : (bih0r[idx - 512] + bhh0r[idx - 512]);
    if (idx < 512)
        g_bias1[idx] = bih1f[idx] + bhh1f[idx];
}

// ---------------- embedding gather -> bf16 hi/lo ----------------
__global__ void embed_kernel(const int* __restrict__ x, const float* __restrict__ emb)
{
    int bt = blockIdx.x;
    int d = threadIdx.x;   // 320 threads
    int ix = x[bt];
    float v = (d < D_) ? emb[(size_t)ix * D_ + d] : 0.0f;
    __nv_bfloat16 hi, lo; bsplit(v, hi, lo);
    g_Ah[(size_t)bt * KP1 + d] = hi;
    g_Al[(size_t)bt * KP1 + d] = lo;
}

// ---------------- HMMA GEMM: C[M][N] = A*B^T + bias, bf16 2-term split ----------------
// CTA 128x128, 8 warps (4 M x 2 N), warp tile 32x64, K-chunk 32.
// Double-buffered smem, ONE __syncthreads per K-chunk.
// smem rows padded to 40 bf16 (80 B) -> conflict-free ldmatrix.
#define PADK 40
#define TILE_ELEMS (128 * PADK)                 // 5120 bf16 per array
#define BUF_ELEMS  (4 * TILE_ELEMS)             // Ah, Al, Bh, Bl
#define GEMM_SMEM  (2 * BUF_ELEMS * 2)          // bytes, 81920

__global__ __launch_bounds__(256) void gemm_mma(
    const __nv_bfloat16* __restrict__ Ah, const __nv_bfloat16* __restrict__ Al,
    const __nv_bfloat16* __restrict__ Bh, const __nv_bfloat16* __restrict__ Bl,
    const float* __restrict__ bias, float* __restrict__ C,
    int Kpad, int NC, int N)
{
    extern __shared__ __nv_bfloat16 sg[];       // [2][4][TILE_ELEMS]

    const int tid = threadIdx.x;
    const int lid = tid & 31, wid = tid >> 5;
    const int wm = wid & 3, wn = wid >> 2;
    const int m0 = blockIdx.y * 128, n0 = blockIdx.x * 128;

    // global-load mapping: thread loads rows (t>>2, t>>2 + 64), cols (t&3)*8
    const int gr = tid >> 2, gc = (tid & 3) * 8;
    const __nv_bfloat16* pAh0 = Ah + (size_t)(m0 + gr) * Kpad + gc;
    const __nv_bfloat16* pAl0 = Al + (size_t)(m0 + gr) * Kpad + gc;
    const __nv_bfloat16* pBh0 = Bh + (size_t)(n0 + gr) * Kpad + gc;
    const __nv_bfloat16* pBl0 = Bl + (size_t)(n0 + gr) * Kpad + gc;
    const size_t rstep = (size_t)64 * Kpad;

    // ldmatrix per-thread source offsets (bytes) within one [128][PADK] tile
    const int aRow = wm * 32 + (lid & 7) + ((lid >> 3) & 1) * 8;
    const int aK   = (lid >> 4) * 8;
    const int bRow = wn * 64 + (lid & 7) + ((lid >> 4) & 1) * 8;
    const int bK   = ((lid >> 3) & 1) * 8;
    const u32 sbase = smem_u32(sg);
    const u32 aOff = (u32)(aRow * (PADK * 2) + aK * 2);
    const u32 bOff = (u32)(bRow * (PADK * 2) + bK * 2);

    float acc[2][8][4];
#pragma unroll
    for (int mt = 0; mt < 2; mt++)
#pragma unroll
        for (int nt = 0; nt < 8; nt++)
#pragma unroll
            for (int j = 0; j < 4; j++) acc[mt][nt][j] = 0.0f;

    uint4 ra[2], rl[2], rb[2], rbl[2];
#pragma unroll
    for (int i = 0; i < 2; i++) {
        ra[i]  = *(const uint4*)(pAh0 + i * rstep);
        rl[i]  = *(const uint4*)(pAl0 + i * rstep);
        rb[i]  = *(const uint4*)(pBh0 + i * rstep);
        rbl[i] = *(const uint4*)(pBl0 + i * rstep);
    }

    for (int c = 0; c < NC; c++) {
        // STS into buffer c&1 (last readers of this buffer were chunk c-2,
        // protected by chunk c-1's barrier) -> one sync per chunk suffices.
        __nv_bfloat16* dst = sg + (c & 1) * BUF_ELEMS;
#pragma unroll
        for (int i = 0; i < 2; i++) {
            int so = (gr + i * 64) * PADK + gc;
            *(uint4*)(dst + so)                  = ra[i];
            *(uint4*)(dst + TILE_ELEMS + so)     = rl[i];
            *(uint4*)(dst + 2 * TILE_ELEMS + so) = rb[i];
            *(uint4*)(dst + 3 * TILE_ELEMS + so) = rbl[i];
        }
        __syncthreads();
        if (c + 1 < NC) {
            int k0 = (c + 1) * 32;
#pragma unroll
            for (int i = 0; i < 2; i++) {
                ra[i]  = *(const uint4*)(pAh0 + i * rstep + k0);
                rl[i]  = *(const uint4*)(pAl0 + i * rstep + k0);
                rb[i]  = *(const uint4*)(pBh0 + i * rstep + k0);
                rbl[i] = *(const uint4*)(pBl0 + i * rstep + k0);
            }
        }
        const u32 bb = sbase + (c & 1) * (BUF_ELEMS * 2);
#pragma unroll
        for (int ks = 0; ks < 2; ks++) {
            const u32 kso = ks * 32;   // 16 elems * 2 bytes
            u32 afh[2][4], afl[2][4];
#pragma unroll
            for (int mt = 0; mt < 2; mt++) {
                u32 off = aOff + mt * 16 * (PADK * 2) + kso;
                LDSM4(afh[mt][0], afh[mt][1], afh[mt][2], afh[mt][3], bb + off);
                LDSM4(afl[mt][0], afl[mt][1], afl[mt][2], afl[mt][3], bb + TILE_ELEMS * 2 + off);
            }
            u32 bfh[4][4], bfl[4][4];
#pragma unroll
            for (int np = 0; np < 4; np++) {
                u32 off = bOff + np * 16 * (PADK * 2) + kso;
                LDSM4(bfh[np][0], bfh[np][1], bfh[np][2], bfh[np][3], bb + 2 * TILE_ELEMS * 2 + off);
                LDSM4(bfl[np][0], bfl[np][1], bfl[np][2], bfl[np][3], bb + 3 * TILE_ELEMS * 2 + off);
            }
#pragma unroll
            for (int mt = 0; mt < 2; mt++) {
#pragma unroll
                for (int np = 0; np < 4; np++) {
#pragma unroll
                    for (int hf = 0; hf < 2; hf++) {
                        int nt = np * 2 + hf;
                        u32 bh[2] = { bfh[np][hf * 2], bfh[np][hf * 2 + 1] };
                        u32 bl[2] = { bfl[np][hf * 2], bfl[np][hf * 2 + 1] };
                        MMA16816(acc[mt][nt], afh[mt], bh);
                        MMA16816(acc[mt][nt], afh[mt], bl);
                        MMA16816(acc[mt][nt], afl[mt], bh);
                    }
                }
            }
        }
    }

    // epilogue
    const int qr = lid >> 2, qc = (lid & 3) * 2;
#pragma unroll
    for (int mt = 0; mt < 2; mt++) {
#pragma unroll
        for (int nt = 0; nt < 8; nt++) {
            int row = m0 + wm * 32 + mt * 16 + qr;
            int col = n0 + wn * 64 + nt * 8 + qc;
            float b0 = bias[col], b1 = bias[col + 1];
            float2 o0 = make_float2(acc[mt][nt][0] + b0, acc[mt][nt][1] + b1);
            float2 o1 = make_float2(acc[mt][nt][2] + b0, acc[mt][nt][3] + b1);
            *(float2*)(C + (size_t)row * N + col) = o0;
            *(float2*)(C + (size_t)(row + 8) * N + col) = o1;
        }
    }
}

// ---------------- LSTM recurrence ----------------
// Thread g owns gate row g. W_hh: 72 cols in regs, 56 cols in smem.
// xg(t+1) prefetched at top of step t; 2 partial accumulators per batch.
#define QREG 18
#define QSM  14

template<bool STORE_ALL, int NB>
__global__ __launch_bounds__(512, 1) void lstm_rec(
    const float* __restrict__ xg, int xg_stride, int goff_per_dir,
    const float* __restrict__ whh_f, const float* __restrict__ whh_r,
    float* __restrict__ hout, int hout_stride, int hcol_per_dir)
{
    extern __shared__ float sm[];
    float4* ws4  = (float4*)sm;                  // [QSM][512]
    float*  h_sm = sm + QSM * 512 * 4;           // [NB][128]
    float*  gates = h_sm + NB * 128;             // [NB][512]

    const int g = threadIdx.x;
    const int dir = blockIdx.y;
    const int b0 = blockIdx.x * NB;
    const float* whh = dir ? whh_r : whh_f;
    const int goff = dir * goff_per_dir;

    u64 wreg[2 * QREG];
    const float4* wrow = (const float4*)(whh + (size_t)g * 128);
#pragma unroll
    for (int q = 0; q < QREG; q++) {
        float4 v = wrow[q];
        wreg[2 * q]     = f2u(v.x, v.y);
        wreg[2 * q + 1] = f2u(v.z, v.w);
    }
#pragma unroll
    for (int q = 0; q < QSM; q++)
        ws4[q * 512 + g] = wrow[QREG + q];

    if (g < NB * 128) h_sm[g] = 0.0f;
    float creg = 0.0f;

    const int t0 = dir ? (T_ - 1) : 0;
    const int tstep = dir ? -1 : 1;
    const long pstep = (long)tstep * xg_stride;
    const float* xp[NB];
#pragma unroll
    for (int u = 0; u < NB; u++)
        xp[u] = xg + (size_t)((b0 + u) * T_ + t0) * xg_stride + goff + g;

    float xv[NB], xn[NB];
#pragma unroll
    for (int u = 0; u < NB; u++) xv[u] = *xp[u];
    __syncthreads();

    for (int s = 0; s < T_; s++) {
        const int t = t0 + s * tstep;
        if (s + 1 < T_) {
#pragma unroll
            for (int u = 0; u < NB; u++) { xp[u] += pstep; xn[u] = *xp[u]; }
        }
        u64 acc0[NB], acc1[NB];
#pragma unroll
        for (int u = 0; u < NB; u++) { acc0[u] = 0ull; acc1[u] = 0ull; }

        // smem-held W first: LDS issued early, covered by the reg-W FMA stream
#pragma unroll
        for (int q = 0; q < QSM; q++) {
            float4 w = ws4[q * 512 + g];
            u64 w01 = f2u(w.x, w.y), w23 = f2u(w.z, w.w);
#pragma unroll
            for (int u = 0; u < NB; u++) {
                float4 h = *(const float4*)(h_sm + u * 128 + (QREG + q) * 4);
                acc0[u] = fma2(w01, f2u(h.x, h.y), acc0[u]);
                acc1[u] = fma2(w23, f2u(h.z, h.w), acc1[u]);
            }
        }
#pragma unroll
        for (int q = 0; q < QREG; q++) {
#pragma unroll
            for (int u = 0; u < NB; u++) {
                float4 h = *(const float4*)(h_sm + u * 128 + q * 4);
                acc0[u] = fma2(wreg[2 * q],     f2u(h.x, h.y), acc0[u]);
                acc1[u] = fma2(wreg[2 * q + 1], f2u(h.z, h.w), acc1[u]);
            }
        }
#pragma unroll
        for (int u = 0; u < NB; u++) {
            float2 a = u2f(acc0[u]), b = u2f(acc1[u]);
            gates[u * 512 + g] = (a.x + a.y) + (b.x + b.y) + xv[u];
        }
        __syncthreads();

        if (g < NB * 128) {
            int bb = g >> 7, n = g & 127;
            const float* gs = gates + bb * 512;
            float iv = sigf_(gs[n]);
            float fv = sigf_(gs[n + 128]);
            float gv = tanhf_(gs[n + 256]);
            float ov = sigf_(gs[n + 384]);
            creg = fv * creg + iv * gv;
            float hv = ov * tanhf_(creg);
            h_sm[bb * 128 + n] = hv;
            int b = b0 + bb;
            if (STORE_ALL) {
                size_t o = (size_t)(b * T_ + t) * hout_stride + dir * hcol_per_dir + n;
                hout[o] = hv;
                __nv_bfloat16 hi, lo; bsplit(hv, hi, lo);
                g_h0h[o] = hi;
                g_h0l[o] = lo;
            } else if (s == T_ - 1) {
                hout[b * H_ + n] = hv;
            }
        }
        __syncthreads();
#pragma unroll
        for (int u = 0; u < NB; u++) xv[u] = xn[u];
    }
}

// ---------------- layer1 reverse (first step only) + FC head ----------------
__global__ __launch_bounds__(256) void tail_kernel(
    const float* __restrict__ h0, const float* __restrict__ h1f,
    const float* __restrict__ wih_r, const float* __restrict__ bih_r,
    const float* __restrict__ bhh_r,
    const float* __restrict__ fc_w, const float* __restrict__ fc_b,
    float* __restrict__ out)
{
    __shared__ float hl[256];
    __shared__ float hcat[256];
    __shared__ float gsm[512];
    int b = blockIdx.x, tid = threadIdx.x;
    hl[tid] = h0[(size_t)(b * T_ + (T_ - 1)) * 256 + tid];
    __syncthreads();

#pragma unroll
    for (int r = 0; r < 2; r++) {
        int g = tid + r * 256;
        u64 acc = 0ull;
        const float4* wr = (const float4*)(wih_r + (size_t)g * 256);
        const float4* hp = (const float4*)hl;
#pragma unroll 8
        for (int q = 0; q < 64; q++) {
            float4 w = wr[q];
            float4 h = hp[q];
            acc = fma2(f2u(w.x, w.y), f2u(h.x, h.y), acc);
            acc = fma2(f2u(w.z, w.w), f2u(h.z, h.w), acc);
        }
        float2 a = u2f(acc);
        gsm[g] = a.x + a.y + bih_r[g] + bhh_r[g];
    }
    __syncthreads();

    if (tid < 128) {
        float iv = sigf_(gsm[tid]);
        float gv = tanhf_(gsm[tid + 256]);
        float ov = sigf_(gsm[tid + 384]);
        float c = iv * gv;
        hcat[128 + tid] = ov * tanhf_(c);
        hcat[tid] = h1f[b * 128 + tid];
    }
    __syncthreads();

    if (tid < 10) {
        float acc = fc_b[tid];
        const float* w = fc_w + tid * 256;
#pragma unroll 8
        for (int j = 0; j < 256; j++) acc += w[j] * hcat[j];
        out[b * 10 + tid] = acc;
    }
}

// ---------------- launch ----------------
extern "C" void kernel_launch(void* const* d_in, const int* in_sizes, int n_in,
                              void* d_out, int out_size)
{
    const int*   x     = (const int*)d_in[0];
    const float* emb   = (const float*)d_in[1];
    const float* wih0f = (const float*)d_in[2];
    const float* whh0f = (const float*)d_in[3];
    const float* bih0f = (const float*)d_in[4];
    const float* bhh0f = (const float*)d_in[5];
    const float* wih0r = (const float*)d_in[6];
    const float* whh0r = (const float*)d_in[7];
    const float* bih0r = (const float*)d_in[8];
    const float* bhh0r = (const float*)d_in[9];
    const float* wih1f = (const float*)d_in[10];
    const float* whh1f = (const float*)d_in[11];
    const float* bih1f = (const float*)d_in[12];
    const float* bhh1f = (const float*)d_in[13];
    const float* wih1r = (const float*)d_in[14];
    const float* bih1r = (const float*)d_in[16];
    const float* bhh1r = (const float*)d_in[17];
    const float* fc_w  = (const float*)d_in[18];
    const float* fc_b  = (const float*)d_in[19];
    float* out = (float*)d_out;

    void *Ah_p, *Al_p, *xg0_p, *h0_p, *h0h_p, *h0l_p, *xg1_p, *h1f_p;
    void *B1h_p, *B1l_p, *B2h_p, *B2l_p, *bias0_p, *bias1_p;
    cudaGetSymbolAddress(&Ah_p,   g_Ah);
    cudaGetSymbolAddress(&Al_p,   g_Al);
    cudaGetSymbolAddress(&xg0_p,  g_xg0);
    cudaGetSymbolAddress(&h0_p,   g_h0);
    cudaGetSymbolAddress(&h0h_p,  g_h0h);
    cudaGetSymbolAddress(&h0l_p,  g_h0l);
    cudaGetSymbolAddress(&xg1_p,  g_xg1);
    cudaGetSymbolAddress(&h1f_p,  g_h1f);
    cudaGetSymbolAddress(&B1h_p,  g_B1h);
    cudaGetSymbolAddress(&B1l_p,  g_B1l);
    cudaGetSymbolAddress(&B2h_p,  g_B2h);
    cudaGetSymbolAddress(&B2l_p,  g_B2l);
    cudaGetSymbolAddress(&bias0_p, g_bias0);
    cudaGetSymbolAddress(&bias1_p, g_bias1);

    const int rec_smem = QSM * 512 * 16 + 2 * 128 * 4 + 2 * 512 * 4;
    cudaFuncSetAttribute(lstm_rec<true, 2>,  cudaFuncAttributeMaxDynamicSharedMemorySize, rec_smem);
    cudaFuncSetAttribute(lstm_rec<false, 1>, cudaFuncAttributeMaxDynamicSharedMemorySize, rec_smem);
    cudaFuncSetAttribute(gemm_mma, cudaFuncAttributeMaxDynamicSharedMemorySize, GEMM_SMEM);

    // 1. weight prep (bf16 split + bias fold)
    prep_kernel<<<(1024 * KP1 + 255) / 256, 256>>>(wih0f, wih0r, wih1f,
                                                   bih0f, bhh0f, bih0r, bhh0r, bih1f, bhh1f);
    // 2. embedding gather -> bf16 hi/lo
    embed_kernel<<<B_ * T_, KP1>>>(x, emb);
    // 3. layer0 input GEMM (HMMA): [65536,320] x [320,1024]
    gemm_mma<<<dim3(8, 512), 256, GEMM_SMEM>>>(
        (const __nv_bfloat16*)Ah_p, (const __nv_bfloat16*)Al_p,
        (const __nv_bfloat16*)B1h_p, (const __nv_bfloat16*)B1l_p,
        (const float*)bias0_p, (float*)xg0_p, KP1, 10, 1024);
    // 4. layer0 recurrence
    lstm_rec<true, 2><<<dim3(64, 2), 512, rec_smem>>>(
        (const float*)xg0_p, 1024, 512, whh0f, whh0r, (float*)h0_p, 256, 128);
    // 5. layer1-fwd input GEMM (HMMA): [65536,256] x [256,512]
    gemm_mma<<<dim3(4, 512), 256, GEMM_SMEM>>>(
        (const __nv_bfloat16*)h0h_p, (const __nv_bfloat16*)h0l_p,
        (const __nv_bfloat16*)B2h_p, (const __nv_bfloat16*)B2l_p,
        (const float*)bias1_p, (float*)xg1_p, KP2, 8, 512);
    // 6. layer1-fwd recurrence
    lstm_rec<false, 1><<<dim3(128, 1), 512, rec_smem>>>(
        (const float*)xg1_p, 512, 0, whh1f, whh1f, (float*)h1f_p, 0, 0);
    // 7. layer1-rev first step + FC head
    tail_kernel<<<B_, 256>>>((const float*)h0_p, (const float*)h1f_p,
                             wih1r, bih1r, bhh1r, fc_w, fc_b, out);
}

// round 6
// speedup vs baseline: 1.8081x; 1.2570x over previous
#include <cuda_runtime.h>
#include <cuda_bf16.h>

typedef unsigned long long u64;
typedef unsigned int u32;

#define B_  128
#define T_  512
#define D_  300
#define H_  128
#define KP1 320   // layer0 K padded (300 -> 320, 10 chunks of 32)
#define KP2 256   // layer1 K (8 chunks of 32)

// ---------------- static device scratch ----------------
__device__ __nv_bfloat16 g_Ah [(size_t)B_ * T_ * KP1];   // embeddings bf16 hi
__device__ __nv_bfloat16 g_Al [(size_t)B_ * T_ * KP1];   // embeddings bf16 lo
__device__ float g_xg0 [(size_t)B_ * T_ * 1024];         // layer0 preacts (fwd 0:512, rev 512:1024)
__device__ float g_h0  [(size_t)B_ * T_ * 256];          // layer0 output fp32 (only t=T-1 written)
__device__ __nv_bfloat16 g_h0h[(size_t)B_ * T_ * 256];   // layer0 output bf16 hi
__device__ __nv_bfloat16 g_h0l[(size_t)B_ * T_ * 256];   // layer0 output bf16 lo
__device__ float g_xg1 [(size_t)B_ * T_ * 512];          // layer1-fwd preacts
__device__ float g_h1f [B_ * H_];
__device__ __nv_bfloat16 g_B1h[1024 * KP1];              // W_ih layer0 (f||r), [n][k]
__device__ __nv_bfloat16 g_B1l[1024 * KP1];
__device__ __nv_bfloat16 g_B2h[512 * KP2];               // W_ih layer1-fwd, [n][k]
__device__ __nv_bfloat16 g_B2l[512 * KP2];
__device__ float g_bias0[1024];
__device__ float g_bias1[512];

// ---------------- scalar helpers ----------------
__device__ __forceinline__ u64 fma2(u64 a, u64 b, u64 c) {
    u64 d;
    asm("fma.rn.f32x2 %0, %1, %2, %3;" : "=l"(d) : "l"(a), "l"(b), "l"(c));
    return d;
}
union F2U { float2 f; u64 u; };
__device__ __forceinline__ u64 f2u(float x, float y) { F2U v; v.f = make_float2(x, y); return v.u; }
__device__ __forceinline__ float2 u2f(u64 u) { F2U v; v.u = u; return v.f; }

__device__ __forceinline__ float sigf_(float x) {
    return __fdividef(1.0f, 1.0f + __expf(-x));
}
__device__ __forceinline__ float tanhf_(float x) {
    float e = __expf(2.0f * x);
    return 1.0f - __fdividef(2.0f, e + 1.0f);
}
__device__ __forceinline__ void bsplit(float v, __nv_bfloat16& hi, __nv_bfloat16& lo) {
    hi = __float2bfloat16(v);
    lo = __float2bfloat16(v - __bfloat162float(hi));
}

__device__ __forceinline__ u32 smem_u32(const void* p) {
    u32 a;
    asm("{ .reg .u64 t; cvta.to.shared.u64 t, %1; cvt.u32.u64 %0, t; }" : "=r"(a) : "l"(p));
    return a;
}

// ---------------- warp-MMA primitives ----------------
#define LDSM4(r0, r1, r2, r3, addr)                                         \
    asm volatile("ldmatrix.sync.aligned.m8n8.x4.shared.b16 {%0,%1,%2,%3}, [%4];" \
        : "=r"(r0), "=r"(r1), "=r"(r2), "=r"(r3) : "r"(addr))

#define MMA16816(d, a, b)                                                   \
    asm volatile("mma.sync.aligned.m16n8k16.row.col.f32.bf16.bf16.f32 "     \
        "{%0,%1,%2,%3}, {%4,%5,%6,%7}, {%8,%9}, {%0,%1,%2,%3};"             \
        : "+f"((d)[0]), "+f"((d)[1]), "+f"((d)[2]), "+f"((d)[3])            \
        : "r"((a)[0]), "r"((a)[1]), "r"((a)[2]), "r"((a)[3]),               \
          "r"((b)[0]), "r"((b)[1]))

// ---------------- weight prep ----------------
__global__ void prep_kernel(const float* __restrict__ wih0f, const float* __restrict__ wih0r,
                            const float* __restrict__ wih1f,
                            const float* __restrict__ bih0f, const float* __restrict__ bhh0f,
                            const float* __restrict__ bih0r, const float* __restrict__ bhh0r,
                            const float* __restrict__ bih1f, const float* __restrict__ bhh1f)
{
    int idx = blockIdx.x * 256 + threadIdx.x;
    if (idx < 1024 * KP1) {
        int n = idx / KP1, k = idx - n * KP1;
        float v = 0.0f;
        if (k < D_) v = (n < 512) ? wih0f[n * D_ + k] : wih0r[(n - 512) * D_ + k];
        __nv_bfloat16 hi, lo; bsplit(v, hi, lo);
        g_B1h[idx] = hi; g_B1l[idx] = lo;
    }
    if (idx < 512 * KP2) {
        __nv_bfloat16 hi, lo; bsplit(wih1f[idx], hi, lo);
        g_B2h[idx] = hi; g_B2l[idx] = lo;
    }
    if (idx < 1024)
        g_bias0[idx] = (idx < 512) ? (bih0f[idx] + bhh0f[idx])
                                   : (bih0r[idx - 512] + bhh0r[idx - 512]);
    if (idx < 512)
        g_bias1[idx] = bih1f[idx] + bhh1f[idx];
}

// ---------------- embedding gather -> bf16 hi/lo (float4 loads, u64 stores) ----------------
__global__ __launch_bounds__(96) void embed_kernel(const int* __restrict__ x,
                                                   const float* __restrict__ emb)
{
    int bt = blockIdx.x;
    int j = threadIdx.x;      // 96 threads; j<75 handle 4 cols each, j 75..79 pad
    if (j >= 80) return;
    int ix = x[bt];
    u64 ph = 0ull, pl = 0ull;
    if (j < 75) {
        float4 v = *(const float4*)(emb + (size_t)ix * 300 + j * 4);
        __nv_bfloat16 h0, l0, h1, l1, h2, l2, h3, l3;
        bsplit(v.x, h0, l0); bsplit(v.y, h1, l1);
        bsplit(v.z, h2, l2); bsplit(v.w, h3, l3);
        u32 a = (u32)*(unsigned short*)&h0 | ((u32)*(unsigned short*)&h1 << 16);
        u32 b = (u32)*(unsigned short*)&h2 | ((u32)*(unsigned short*)&h3 << 16);
        ph = (u64)a | ((u64)b << 32);
        a = (u32)*(unsigned short*)&l0 | ((u32)*(unsigned short*)&l1 << 16);
        b = (u32)*(unsigned short*)&l2 | ((u32)*(unsigned short*)&l3 << 16);
        pl = (u64)a | ((u64)b << 32);
    }
    size_t o = (size_t)bt * KP1 + j * 4;
    *(u64*)(g_Ah + o) = ph;
    *(u64*)(g_Al + o) = pl;
}

// ---------------- HMMA GEMM (unchanged from R5) ----------------
#define PADK 40
#define TILE_ELEMS (128 * PADK)
#define BUF_ELEMS  (4 * TILE_ELEMS)
#define GEMM_SMEM  (2 * BUF_ELEMS * 2)

__global__ __launch_bounds__(256) void gemm_mma(
    const __nv_bfloat16* __restrict__ Ah, const __nv_bfloat16* __restrict__ Al,
    const __nv_bfloat16* __restrict__ Bh, const __nv_bfloat16* __restrict__ Bl,
    const float* __restrict__ bias, float* __restrict__ C,
    int Kpad, int NC, int N)
{
    extern __shared__ __nv_bfloat16 sg[];

    const int tid = threadIdx.x;
    const int lid = tid & 31, wid = tid >> 5;
    const int wm = wid & 3, wn = wid >> 2;
    const int m0 = blockIdx.y * 128, n0 = blockIdx.x * 128;

    const int gr = tid >> 2, gc = (tid & 3) * 8;
    const __nv_bfloat16* pAh0 = Ah + (size_t)(m0 + gr) * Kpad + gc;
    const __nv_bfloat16* pAl0 = Al + (size_t)(m0 + gr) * Kpad + gc;
    const __nv_bfloat16* pBh0 = Bh + (size_t)(n0 + gr) * Kpad + gc;
    const __nv_bfloat16* pBl0 = Bl + (size_t)(n0 + gr) * Kpad + gc;
    const size_t rstep = (size_t)64 * Kpad;

    const int aRow = wm * 32 + (lid & 7) + ((lid >> 3) & 1) * 8;
    const int aK   = (lid >> 4) * 8;
    const int bRow = wn * 64 + (lid & 7) + ((lid >> 4) & 1) * 8;
    const int bK   = ((lid >> 3) & 1) * 8;
    const u32 sbase = smem_u32(sg);
    const u32 aOff = (u32)(aRow * (PADK * 2) + aK * 2);
    const u32 bOff = (u32)(bRow * (PADK * 2) + bK * 2);

    float acc[2][8][4];
#pragma unroll
    for (int mt = 0; mt < 2; mt++)
#pragma unroll
        for (int nt = 0; nt < 8; nt++)
#pragma unroll
            for (int j = 0; j < 4; j++) acc[mt][nt][j] = 0.0f;

    uint4 ra[2], rl[2], rb[2], rbl[2];
#pragma unroll
    for (int i = 0; i < 2; i++) {
        ra[i]  = *(const uint4*)(pAh0 + i * rstep);
        rl[i]  = *(const uint4*)(pAl0 + i * rstep);
        rb[i]  = *(const uint4*)(pBh0 + i * rstep);
        rbl[i] = *(const uint4*)(pBl0 + i * rstep);
    }

    for (int c = 0; c < NC; c++) {
        __nv_bfloat16* dst = sg + (c & 1) * BUF_ELEMS;
#pragma unroll
        for (int i = 0; i < 2; i++) {
            int so = (gr + i * 64) * PADK + gc;
            *(uint4*)(dst + so)                  = ra[i];
            *(uint4*)(dst + TILE_ELEMS + so)     = rl[i];
            *(uint4*)(dst + 2 * TILE_ELEMS + so) = rb[i];
            *(uint4*)(dst + 3 * TILE_ELEMS + so) = rbl[i];
        }
        __syncthreads();
        if (c + 1 < NC) {
            int k0 = (c + 1) * 32;
#pragma unroll
            for (int i = 0; i < 2; i++) {
                ra[i]  = *(const uint4*)(pAh0 + i * rstep + k0);
                rl[i]  = *(const uint4*)(pAl0 + i * rstep + k0);
                rb[i]  = *(const uint4*)(pBh0 + i * rstep + k0);
                rbl[i] = *(const uint4*)(pBl0 + i * rstep + k0);
            }
        }
        const u32 bb = sbase + (c & 1) * (BUF_ELEMS * 2);
#pragma unroll
        for (int ks = 0; ks < 2; ks++) {
            const u32 kso = ks * 32;
            u32 afh[2][4], afl[2][4];
#pragma unroll
            for (int mt = 0; mt < 2; mt++) {
                u32 off = aOff + mt * 16 * (PADK * 2) + kso;
                LDSM4(afh[mt][0], afh[mt][1], afh[mt][2], afh[mt][3], bb + off);
                LDSM4(afl[mt][0], afl[mt][1], afl[mt][2], afl[mt][3], bb + TILE_ELEMS * 2 + off);
            }
            u32 bfh[4][4], bfl[4][4];
#pragma unroll
            for (int np = 0; np < 4; np++) {
                u32 off = bOff + np * 16 * (PADK * 2) + kso;
                LDSM4(bfh[np][0], bfh[np][1], bfh[np][2], bfh[np][3], bb + 2 * TILE_ELEMS * 2 + off);
                LDSM4(bfl[np][0], bfl[np][1], bfl[np][2], bfl[np][3], bb + 3 * TILE_ELEMS * 2 + off);
            }
#pragma unroll
            for (int mt = 0; mt < 2; mt++) {
#pragma unroll
                for (int np = 0; np < 4; np++) {
#pragma unroll
                    for (int hf = 0; hf < 2; hf++) {
                        int nt = np * 2 + hf;
                        u32 bh[2] = { bfh[np][hf * 2], bfh[np][hf * 2 + 1] };
                        u32 bl[2] = { bfl[np][hf * 2], bfl[np][hf * 2 + 1] };
                        MMA16816(acc[mt][nt], afh[mt], bh);
                        MMA16816(acc[mt][nt], afh[mt], bl);
                        MMA16816(acc[mt][nt], afl[mt], bh);
                    }
                }
            }
        }
    }

    const int qr = lid >> 2, qc = (lid & 3) * 2;
#pragma unroll
    for (int mt = 0; mt < 2; mt++) {
#pragma unroll
        for (int nt = 0; nt < 8; nt++) {
            int row = m0 + wm * 32 + mt * 16 + qr;
            int col = n0 + wn * 64 + nt * 8 + qc;
            float b0 = bias[col], b1 = bias[col + 1];
            float2 o0 = make_float2(acc[mt][nt][0] + b0, acc[mt][nt][1] + b1);
            float2 o1 = make_float2(acc[mt][nt][2] + b0, acc[mt][nt][3] + b1);
            *(float2*)(C + (size_t)row * N + col) = o0;
            *(float2*)(C + (size_t)(row + 8) * N + col) = o1;
        }
    }
}

// ---------------- LSTM recurrence v2: 256 threads, 2 gate rows/thread ----------------
// Thread owns rows (tid, tid+256). CREG=96 cols/row in registers (192 regs),
// CSM=32 cols/row in smem. h float4 broadcast feeds 4 fma2 (2 rows).
#define CREG 96
#define QR_  (CREG / 4)          // 24 float4 groups in regs
#define QS_  ((128 - CREG) / 4)  // 8 float4 groups in smem
// smem: weights QS_*2*256 float4 (65536B) + h[NB*128] + gates[NB*512]

template<bool STORE_ALL, int NB, int XSTR>
__global__ __launch_bounds__(256, 1) void lstm_rec2(
    const float* __restrict__ xg, int goff,
    const float* __restrict__ whh_f, const float* __restrict__ whh_r,
    float* __restrict__ hout)
{
    extern __shared__ float sm[];
    float4* wsm  = (float4*)sm;                    // [QS_][2][256]
    float*  h_sm = sm + QS_ * 2 * 256 * 4;         // [NB][128]
    float*  gsm  = h_sm + NB * 128;                // [NB][512]

    const int tid = threadIdx.x;
    const int dir = blockIdx.y;
    const int b0 = blockIdx.x * NB;
    const float* whh = dir ? whh_r : whh_f;
    const int go = dir ? goff : 0;

    // load weights: rows tid and tid+256
    u64 w0[CREG / 2], w1[CREG / 2];
    {
        const float4* wr0 = (const float4*)(whh + (size_t)tid * 128);
        const float4* wr1 = (const float4*)(whh + (size_t)(tid + 256) * 128);
#pragma unroll
        for (int q = 0; q < QR_; q++) {
            float4 v0 = wr0[q], v1 = wr1[q];
            w0[2 * q] = f2u(v0.x, v0.y); w0[2 * q + 1] = f2u(v0.z, v0.w);
            w1[2 * q] = f2u(v1.x, v1.y); w1[2 * q + 1] = f2u(v1.z, v1.w);
        }
#pragma unroll
        for (int q = 0; q < QS_; q++) {
            wsm[(q * 2 + 0) * 256 + tid] = wr0[QR_ + q];
            wsm[(q * 2 + 1) * 256 + tid] = wr1[QR_ + q];
        }
    }
    if (tid < NB * 128) h_sm[tid] = 0.0f;
    float creg = 0.0f;

    const int t0 = dir ? (T_ - 1) : 0;
    const int tstep = dir ? -1 : 1;
    const float* px[NB];
#pragma unroll
    for (int u = 0; u < NB; u++)
        px[u] = xg + (size_t)(b0 + u) * T_ * XSTR + go + tid;
    long toff = (long)t0 * XSTR;
    const long tdelta = (long)tstep * XSTR;

    // xv[row][batch]
    float xv[2][NB], xn[2][NB];
#pragma unroll
    for (int u = 0; u < NB; u++) {
        xv[0][u] = px[u][toff];
        xv[1][u] = px[u][toff + 256];
    }
    __syncthreads();

    for (int s = 0; s < T_; s++) {
        const int t = t0 + s * tstep;
        if (s + 1 < T_) {
            long tn = toff + tdelta;
#pragma unroll
            for (int u = 0; u < NB; u++) {
                xn[0][u] = px[u][tn];
                xn[1][u] = px[u][tn + 256];
            }
            toff = tn;
        }

        u64 a0[NB], a1[NB];    // acc row0, row1 per batch
#pragma unroll
        for (int u = 0; u < NB; u++) { a0[u] = 0ull; a1[u] = 0ull; }

        // smem-weight portion first (LDS issued early)
#pragma unroll
        for (int q = 0; q < QS_; q++) {
            float4 q0 = wsm[(q * 2 + 0) * 256 + tid];
            float4 q1 = wsm[(q * 2 + 1) * 256 + tid];
            u64 w0a = f2u(q0.x, q0.y), w0b = f2u(q0.z, q0.w);
            u64 w1a = f2u(q1.x, q1.y), w1b = f2u(q1.z, q1.w);
#pragma unroll
            for (int u = 0; u < NB; u++) {
                float4 h = *(const float4*)(h_sm + u * 128 + (QR_ + q) * 4);
                u64 ha = f2u(h.x, h.y), hb = f2u(h.z, h.w);
                a0[u] = fma2(w0a, ha, a0[u]); a0[u] = fma2(w0b, hb, a0[u]);
                a1[u] = fma2(w1a, ha, a1[u]); a1[u] = fma2(w1b, hb, a1[u]);
            }
        }
        // register-weight portion
#pragma unroll
        for (int q = 0; q < QR_; q++) {
#pragma unroll
            for (int u = 0; u < NB; u++) {
                float4 h = *(const float4*)(h_sm + u * 128 + q * 4);
                u64 ha = f2u(h.x, h.y), hb = f2u(h.z, h.w);
                a0[u] = fma2(w0[2 * q], ha, a0[u]); a0[u] = fma2(w0[2 * q + 1], hb, a0[u]);
                a1[u] = fma2(w1[2 * q], ha, a1[u]); a1[u] = fma2(w1[2 * q + 1], hb, a1[u]);
            }
        }
#pragma unroll
        for (int u = 0; u < NB; u++) {
            float2 r0 = u2f(a0[u]), r1 = u2f(a1[u]);
            gsm[u * 512 + tid]       = r0.x + r0.y + xv[0][u];
            gsm[u * 512 + tid + 256] = r1.x + r1.y + xv[1][u];
        }
        __syncthreads();

        if (NB == 2 || tid < 128) {
            const int bb = (NB == 2) ? (tid >> 7) : 0;
            const int n = tid & 127;
            const float* gs = gsm + bb * 512;
            float iv = sigf_(gs[n]);
            float fv = sigf_(gs[n + 128]);
            float gv = tanhf_(gs[n + 256]);
            float ov = sigf_(gs[n + 384]);
            creg = fv * creg + iv * gv;
            float hv = ov * tanhf_(creg);
            h_sm[bb * 128 + n] = hv;
            const int b = b0 + bb;
            if (STORE_ALL) {
                size_t o = ((size_t)b * T_ + t) * 256 + dir * 128 + n;
                __nv_bfloat16 hi, lo; bsplit(hv, hi, lo);
                g_h0h[o] = hi;
                g_h0l[o] = lo;
                if (t == T_ - 1) g_h0[o] = hv;   // tail only needs last timestep
            } else if (s == T_ - 1) {
                hout[b * H_ + n] = hv;
            }
        }
        __syncthreads();
#pragma unroll
        for (int u = 0; u < NB; u++) { xv[0][u] = xn[0][u]; xv[1][u] = xn[1][u]; }
    }
}

// ---------------- layer1 reverse (first step only) + FC head ----------------
__global__ __launch_bounds__(256) void tail_kernel(
    const float* __restrict__ h0, const float* __restrict__ h1f,
    const float* __restrict__ wih_r, const float* __restrict__ bih_r,
    const float* __restrict__ bhh_r,
    const float* __restrict__ fc_w, const float* __restrict__ fc_b,
    float* __restrict__ out)
{
    __shared__ float hl[256];
    __shared__ float hcat[256];
    __shared__ float gsm[512];
    int b = blockIdx.x, tid = threadIdx.x;
    hl[tid] = h0[(size_t)(b * T_ + (T_ - 1)) * 256 + tid];
    __syncthreads();

#pragma unroll
    for (int r = 0; r < 2; r++) {
        int g = tid + r * 256;
        u64 acc = 0ull;
        const float4* wr = (const float4*)(wih_r + (size_t)g * 256);
        const float4* hp = (const float4*)hl;
#pragma unroll 8
        for (int q = 0; q < 64; q++) {
            float4 w = wr[q];
            float4 h = hp[q];
            acc = fma2(f2u(w.x, w.y), f2u(h.x, h.y), acc);
            acc = fma2(f2u(w.z, w.w), f2u(h.z, h.w), acc);
        }
        float2 a = u2f(acc);
        gsm[g] = a.x + a.y + bih_r[g] + bhh_r[g];
    }
    __syncthreads();

    if (tid < 128) {
        float iv = sigf_(gsm[tid]);
        float gv = tanhf_(gsm[tid + 256]);
        float ov = sigf_(gsm[tid + 384]);
        float c = iv * gv;
        hcat[128 + tid] = ov * tanhf_(c);
        hcat[tid] = h1f[b * 128 + tid];
    }
    __syncthreads();

    if (tid < 10) {
        float acc = fc_b[tid];
        const float* w = fc_w + tid * 256;
#pragma unroll 8
        for (int j = 0; j < 256; j++) acc += w[j] * hcat[j];
        out[b * 10 + tid] = acc;
    }
}

// ---------------- launch ----------------
extern "C" void kernel_launch(void* const* d_in, const int* in_sizes, int n_in,
                              void* d_out, int out_size)
{
    const int*   x     = (const int*)d_in[0];
    const float* emb   = (const float*)d_in[1];
    const float* wih0f = (const float*)d_in[2];
    const float* whh0f = (const float*)d_in[3];
    const float* bih0f = (const float*)d_in[4];
    const float* bhh0f = (const float*)d_in[5];
    const float* wih0r = (const float*)d_in[6];
    const float* whh0r = (const float*)d_in[7];
    const float* bih0r = (const float*)d_in[8];
    const float* bhh0r = (const float*)d_in[9];
    const float* wih1f = (const float*)d_in[10];
    const float* whh1f = (const float*)d_in[11];
    const float* bih1f = (const float*)d_in[12];
    const float* bhh1f = (const float*)d_in[13];
    const float* wih1r = (const float*)d_in[14];
    const float* bih1r = (const float*)d_in[16];
    const float* bhh1r = (const float*)d_in[17];
    const float* fc_w  = (const float*)d_in[18];
    const float* fc_b  = (const float*)d_in[19];
    float* out = (float*)d_out;

    void *Ah_p, *Al_p, *xg0_p, *h0_p, *h0h_p, *h0l_p, *xg1_p, *h1f_p;
    void *B1h_p, *B1l_p, *B2h_p, *B2l_p, *bias0_p, *bias1_p;
    cudaGetSymbolAddress(&Ah_p,   g_Ah);
    cudaGetSymbolAddress(&Al_p,   g_Al);
    cudaGetSymbolAddress(&xg0_p,  g_xg0);
    cudaGetSymbolAddress(&h0_p,   g_h0);
    cudaGetSymbolAddress(&h0h_p,  g_h0h);
    cudaGetSymbolAddress(&h0l_p,  g_h0l);
    cudaGetSymbolAddress(&xg1_p,  g_xg1);
    cudaGetSymbolAddress(&h1f_p,  g_h1f);
    cudaGetSymbolAddress(&B1h_p,  g_B1h);
    cudaGetSymbolAddress(&B1l_p,  g_B1l);
    cudaGetSymbolAddress(&B2h_p,  g_B2h);
    cudaGetSymbolAddress(&B2l_p,  g_B2l);
    cudaGetSymbolAddress(&bias0_p, g_bias0);
    cudaGetSymbolAddress(&bias1_p, g_bias1);

    const int ws_bytes = QS_ * 2 * 256 * 16;                  // 65536
    const int rec_smem2 = ws_bytes + 2 * 128 * 4 + 2 * 512 * 4;   // NB=2
    const int rec_smem1 = ws_bytes + 1 * 128 * 4 + 1 * 512 * 4;   // NB=1
    cudaFuncSetAttribute(lstm_rec2<true, 2, 1024>, cudaFuncAttributeMaxDynamicSharedMemorySize, rec_smem2);
    cudaFuncSetAttribute(lstm_rec2<false, 1, 512>, cudaFuncAttributeMaxDynamicSharedMemorySize, rec_smem1);
    cudaFuncSetAttribute(gemm_mma, cudaFuncAttributeMaxDynamicSharedMemorySize, GEMM_SMEM);

    // 1. weight prep (bf16 split + bias fold)
    prep_kernel<<<(1024 * KP1 + 255) / 256, 256>>>(wih0f, wih0r, wih1f,
                                                   bih0f, bhh0f, bih0r, bhh0r, bih1f, bhh1f);
    // 2. embedding gather -> bf16 hi/lo
    embed_kernel<<<B_ * T_, 96>>>(x, emb);
    // 3. layer0 input GEMM (HMMA): [65536,320] x [320,1024]
    gemm_mma<<<dim3(8, 512), 256, GEMM_SMEM>>>(
        (const __nv_bfloat16*)Ah_p, (const __nv_bfloat16*)Al_p,
        (const __nv_bfloat16*)B1h_p, (const __nv_bfloat16*)B1l_p,
        (const float*)bias0_p, (float*)xg0_p, KP1, 10, 1024);
    // 4. layer0 recurrence (NB=2, both dirs -> 128 CTAs of 256 threads)
    lstm_rec2<true, 2, 1024><<<dim3(64, 2), 256, rec_smem2>>>(
        (const float*)xg0_p, 512, whh0f, whh0r, (float*)h0_p);
    // 5. layer1-fwd input GEMM (HMMA): [65536,256] x [256,512]
    gemm_mma<<<dim3(4, 512), 256, GEMM_SMEM>>>(
        (const __nv_bfloat16*)h0h_p, (const __nv_bfloat16*)h0l_p,
        (const __nv_bfloat16*)B2h_p, (const __nv_bfloat16*)B2l_p,
        (const float*)bias1_p, (float*)xg1_p, KP2, 8, 512);
    // 6. layer1-fwd recurrence (NB=1 -> 128 CTAs of 256 threads)
    lstm_rec2<false, 1, 512><<<dim3(128, 1), 256, rec_smem1>>>(
        (const float*)xg1_p, 0, whh1f, whh1f, (float*)h1f_p);
    // 7. layer1-rev first step + FC head
    tail_kernel<<<B_, 256>>>((const float*)h0_p, (const float*)h1f_p,
                             wih1r, bih1r, bhh1r, fc_w, fc_b, out);
}